// round 16
// baseline (speedup 1.0000x reference)
#include <cuda_runtime.h>
#include <cuda_bf16.h>
#include <math.h>
#include <cstdint>

#define BD   1024
#define HD   512
#define TENC 384
#define TDEC 128
#define ID   128
#define NBLK 128
#define NTHR 384           // 8 consumer warps + 4 producer warps

#define ROWB 144           // smem row stride bytes (64 bf16 = 128B + 16B pad)
#define TILEB (128 * ROWB) // 18432 per operand tile
#define STB  (2 * TILEB)   // 36864 per stage (A + B)
#define NST  4             // ring depth (power of two)
#define ZBF  (128 * 132)   // z-buffer floats (separate from ring)

#define BAR_CNT 384        // FULL[st]=1+st (cnt384), EMPTY[st]=5+st (cnt384)
#define NGRP   8           // m-groups of 16 CTAs each

// ---------------- static device scratch ------------------------------------
__device__ __align__(16) __nv_bfloat16 g_hA[BD * 1024];   // ping-pong [h0|h1]
__device__ __align__(16) __nv_bfloat16 g_hB[BD * 1024];
__device__ __align__(16) float         g_h1f[BD * HD];    // fp32 h1 for fc
__device__ __align__(16) float g_c0 [BD * HD];
__device__ __align__(16) float g_c1 [BD * HD];
__device__ __align__(16) __nv_bfloat16 g_din[BD * ID];
__device__ __align__(16) __nv_bfloat16 g_xb [BD * TENC * ID];   // bf16 x copy
__device__ __align__(16) __nv_bfloat16 g_rWih0[2048 * 128];
__device__ __align__(16) __nv_bfloat16 g_rWhh0[2048 * 512];
__device__ __align__(16) __nv_bfloat16 g_rWih1[2048 * 512];
__device__ __align__(16) __nv_bfloat16 g_rWhh1[2048 * 512];
__device__ unsigned          g_bar_cnt;
__device__ volatile unsigned g_bar_gen;
__device__ unsigned          g_gcnt[NGRP * 64];
__device__ volatile unsigned g_ggen[NGRP * 64];

// ---------------- helpers --------------------------------------------------
__device__ __forceinline__ uint32_t smem_u32(const void* p) {
    uint32_t a;
    asm("{ .reg .u64 t; cvta.to.shared.u64 t, %1; cvt.u32.u64 %0, t; }"
        : "=r"(a) : "l"(p));
    return a;
}
__device__ __forceinline__ float tanh_a(float x) {
    float r;
    asm("tanh.approx.f32 %0, %1;" : "=f"(r) : "f"(x));
    return r;
}
__device__ __forceinline__ float sig_a(float x) {
    return fmaf(0.5f, tanh_a(0.5f * x), 0.5f);
}
__device__ __forceinline__ void cp16(uint32_t dst, const void* src) {
    asm volatile("cp.async.cg.shared.global [%0], [%1], 16;"
                 :: "r"(dst), "l"(src) : "memory");
}
__device__ __forceinline__ void mma16(float* c, uint32_t a0, uint32_t a1,
                                      uint32_t a2, uint32_t a3,
                                      uint32_t b0, uint32_t b1) {
    asm volatile("mma.sync.aligned.m16n8k16.row.col.f32.bf16.bf16.f32 "
                 "{%0,%1,%2,%3}, {%4,%5,%6,%7}, {%8,%9}, {%0,%1,%2,%3};"
                 : "+f"(c[0]), "+f"(c[1]), "+f"(c[2]), "+f"(c[3])
                 : "r"(a0), "r"(a1), "r"(a2), "r"(a3), "r"(b0), "r"(b1));
}
#define LDSM4(r, a)                                                          \
    asm volatile("ldmatrix.sync.aligned.m8n8.x4.shared.b16 {%0,%1,%2,%3}, [%4];" \
        : "=r"((r)[0]), "=r"((r)[1]), "=r"((r)[2]), "=r"((r)[3]) : "r"(a))

__device__ __forceinline__ float4 ldcg4(const float* p) {
    float4 v;
    asm volatile("ld.global.cg.v4.f32 {%0,%1,%2,%3}, [%4];"
                 : "=f"(v.x), "=f"(v.y), "=f"(v.z), "=f"(v.w) : "l"(p));
    return v;
}
__device__ __forceinline__ void bar_sync(int id) {
    asm volatile("bar.sync %0, %1;" :: "r"(id), "n"(BAR_CNT) : "memory");
}
__device__ __forceinline__ void bar_arrive(int id) {
    asm volatile("bar.arrive %0, %1;" :: "r"(id), "n"(BAR_CNT) : "memory");
}
__device__ __forceinline__ void bar9() {           // consumer-only barrier
    asm volatile("bar.sync 9, 256;" ::: "memory");
}

// ---------------- barriers ---------------------------------------------------
__device__ __forceinline__ void gridbar() {
    __syncthreads();
    if (threadIdx.x == 0) {
        unsigned gen = g_bar_gen;
        __threadfence();
        if (atomicAdd(&g_bar_cnt, 1u) == NBLK - 1u) {
            g_bar_cnt = 0u;
            __threadfence();
            g_bar_gen = gen + 1u;
        } else {
            while (g_bar_gen == gen) { __nanosleep(32); }
        }
        __threadfence();
    }
    __syncthreads();
}
__device__ __forceinline__ void groupbar() {
    const int gq = (blockIdx.x >> 4) * 64;
    __syncthreads();
    if (threadIdx.x == 0) {
        unsigned gen = g_ggen[gq];
        __threadfence();
        if (atomicAdd(&g_gcnt[gq], 1u) == 15u) {
            g_gcnt[gq] = 0u;
            __threadfence();
            g_ggen[gq] = gen + 1u;
        } else {
            while (g_ggen[gq] == gen) { __nanosleep(32); }
        }
        __threadfence();
    }
    __syncthreads();
}

// ---------------- init ------------------------------------------------------
__device__ __forceinline__ uint32_t packbf(float a, float b) {
    __nv_bfloat162 v = __floats2bfloat162_rn(a, b);
    return *(uint32_t*)&v;
}
__device__ void cvt_arr(const float* __restrict__ src, __nv_bfloat16* dst,
                        int n, int g, int GT)
{
    const float4* s4 = (const float4*)src;
    uint2* d4 = (uint2*)dst;
    for (int i = g; i < n / 4; i += GT) {
        float4 v = s4[i];
        d4[i] = make_uint2(packbf(v.x, v.y), packbf(v.z, v.w));
    }
}
__device__ void init_phase(const float* __restrict__ x,
                           const float* __restrict__ Wih0,
                           const float* __restrict__ Whh0,
                           const float* __restrict__ Wih1,
                           const float* __restrict__ Whh1)
{
    const int g = blockIdx.x * NTHR + threadIdx.x;
    const int GT = NBLK * NTHR;
    uint32_t* hA = (uint32_t*)g_hA;
    uint32_t* hB = (uint32_t*)g_hB;
    for (int i = g; i < BD * 1024 / 2; i += GT) { hA[i] = 0u; hB[i] = 0u; }
    for (int i = g; i < BD * HD; i += GT) { g_c0[i] = 0.f; g_c1[i] = 0.f; }
    for (int i = g; i < BD * ID; i += GT) {
        int b = i >> 7, col = i & 127;
        g_din[i] = __float2bfloat16(
            x[(size_t)b * (TENC * ID) + (size_t)(TENC - 1) * ID + col]);
    }
    cvt_arr(x,    g_xb,    BD * TENC * ID, g, GT);
    cvt_arr(Wih0, g_rWih0, 2048 * 128, g, GT);
    cvt_arr(Whh0, g_rWhh0, 2048 * 512, g, GT);
    cvt_arr(Wih1, g_rWih1, 2048 * 512, g, GT);
    cvt_arr(Whh1, g_rWhh1, 2048 * 512, g, GT);
}

// ---------------- fused phase: up to 2 independent layer-GEMMs in one pipe ---
// d0: layer0 (K=640: A1x[128] | h0prev[512]); d1: layer1 (K=1024: h0cur | h1prev)
// One continuous chunk stream; consumer does a mid-stream epilogue for layer0
// while the producer keeps the ring filled with layer1 chunks.
__device__ void phase_fused(char* ring, float* zb, const float* sbias,
                            int d0, int d1,
                            const __nv_bfloat16* a1x, size_t ldax,
                            const __nv_bfloat16* h0prev,
                            float* c0buf, __nv_bfloat16* h0dst,
                            const __nv_bfloat16* h0cur,
                            const __nv_bfloat16* h1prev,
                            float* c1buf, __nv_bfloat16* h1dst, float* h1fp)
{
    const int tid  = threadIdx.x;
    const int warp = tid >> 5, lane = tid & 31;
    const int m0 = (blockIdx.x >> 4) * 128;
    const int j0 = (blockIdx.x & 15) * 32;
    const int n0  = d0 ? 10 : 0;
    const int nch = n0 + (d1 ? 16 : 0);

    const uint32_t sA = smem_u32(ring);
    const uint32_t sB = sA + (uint32_t)TILEB;

    if (warp >= 8) {
        // ================= producer: continuous stream =================
        const int pr = tid - 256;
        const uint32_t dA = sA + (uint32_t)pr * ROWB;
        const uint32_t dB = sB + (uint32_t)pr * ROWB;
        const int nrow = (pr >> 5) * 512 + j0 + (pr & 31);
        const __nv_bfloat16 *a1r = 0, *a2r = 0, *w1r = 0, *w2r = 0;
        if (d0) {
            a1r = a1x + (size_t)(m0 + pr) * ldax;
            a2r = h0prev + (size_t)(m0 + pr) * 1024 - 128;
            w1r = g_rWih0 + (size_t)nrow * 128;
            w2r = g_rWhh0 + (size_t)nrow * 512 - 128;
        }
        const __nv_bfloat16 *a3r = 0, *a4r = 0, *w3r = 0, *w4r = 0;
        if (d1) {
            a3r = h0cur + (size_t)(m0 + pr) * 1024;
            a4r = h1prev + (size_t)(m0 + pr) * 1024 - 512;
            w3r = g_rWih1 + (size_t)nrow * 512;
            w4r = g_rWhh1 + (size_t)nrow * 512 - 512;
        }
        for (int ch = 0; ch < nch; ch++) {
            int st = ch & (NST - 1);
            bar_sync(5 + st);
            const __nv_bfloat16 *srcA, *srcB;
            if (ch < n0) {
                int k0 = ch * 64;
                srcA = (k0 < 128 ? a1r : a2r) + k0;
                srcB = (k0 < 128 ? w1r : w2r) + k0;
            } else {
                int k0 = (ch - n0) * 64;
                srcA = (k0 < 512 ? a3r : a4r) + k0;
                srcB = (k0 < 512 ? w3r : w4r) + k0;
            }
            uint32_t da = dA + (uint32_t)st * STB;
            uint32_t db = dB + (uint32_t)st * STB;
#pragma unroll
            for (int q = 0; q < 8; q++) {
                cp16(da + q * 16u, srcA + q * 8);
                cp16(db + q * 16u, srcB + q * 8);
            }
            asm volatile("cp.async.commit_group;" ::: "memory");
            if (ch > 0) {
                asm volatile("cp.async.wait_group 1;" ::: "memory");
                bar_arrive(1 + ((ch - 1) & (NST - 1)));
            }
        }
        asm volatile("cp.async.wait_group 0;" ::: "memory");
        bar_arrive(1 + ((nch - 1) & (NST - 1)));
    } else {
        // ================= consumer =================
        const int wm = (warp >> 2) * 64;
        const int wn = (warp & 3) * 32;
        const uint32_t offA = sA + (uint32_t)((lane & 15) * ROWB)
                                 + (uint32_t)((lane >> 4) * 16)
                                 + (uint32_t)wm * ROWB;
        const uint32_t offB = sB + (uint32_t)((lane & 15) * ROWB)
                                 + (uint32_t)((lane >> 4) * 16)
                                 + (uint32_t)wn * ROWB;

        float acc[4][4][4];

        auto consume = [&](int chb, int n) {
            for (int ch = chb; ch < chb + n; ch++) {
                int st = ch & (NST - 1);
                bar_sync(1 + st);
                const uint32_t so = (uint32_t)st * STB;
#pragma unroll
                for (int ks = 0; ks < 4; ks++) {
                    const uint32_t ko = (uint32_t)(ks * 32);
                    uint32_t fb0[4], fb1[4], fa0[4], fa1[4], fa2[4], fa3[4];
                    LDSM4(fb0, offB + so + ko);
                    LDSM4(fb1, offB + so + 16u * ROWB + ko);
                    LDSM4(fa0, offA + so + ko);
                    LDSM4(fa1, offA + so + 16u * ROWB + ko);
                    LDSM4(fa2, offA + so + 32u * ROWB + ko);
                    LDSM4(fa3, offA + so + 48u * ROWB + ko);
                    mma16(acc[0][0], fa0[0], fa0[1], fa0[2], fa0[3], fb0[0], fb0[2]);
                    mma16(acc[0][1], fa0[0], fa0[1], fa0[2], fa0[3], fb0[1], fb0[3]);
                    mma16(acc[0][2], fa0[0], fa0[1], fa0[2], fa0[3], fb1[0], fb1[2]);
                    mma16(acc[0][3], fa0[0], fa0[1], fa0[2], fa0[3], fb1[1], fb1[3]);
                    mma16(acc[1][0], fa1[0], fa1[1], fa1[2], fa1[3], fb0[0], fb0[2]);
                    mma16(acc[1][1], fa1[0], fa1[1], fa1[2], fa1[3], fb0[1], fb0[3]);
                    mma16(acc[1][2], fa1[0], fa1[1], fa1[2], fa1[3], fb1[0], fb1[2]);
                    mma16(acc[1][3], fa1[0], fa1[1], fa1[2], fa1[3], fb1[1], fb1[3]);
                    mma16(acc[2][0], fa2[0], fa2[1], fa2[2], fa2[3], fb0[0], fb0[2]);
                    mma16(acc[2][1], fa2[0], fa2[1], fa2[2], fa2[3], fb0[1], fb0[3]);
                    mma16(acc[2][2], fa2[0], fa2[1], fa2[2], fa2[3], fb1[0], fb1[2]);
                    mma16(acc[2][3], fa2[0], fa2[1], fa2[2], fa2[3], fb1[1], fb1[3]);
                    mma16(acc[3][0], fa3[0], fa3[1], fa3[2], fa3[3], fb0[0], fb0[2]);
                    mma16(acc[3][1], fa3[0], fa3[1], fa3[2], fa3[3], fb0[1], fb0[3]);
                    mma16(acc[3][2], fa3[0], fa3[1], fa3[2], fa3[3], fb1[0], fb1[2]);
                    mma16(acc[3][3], fa3[0], fa3[1], fa3[2], fa3[3], fb1[1], fb1[3]);
                }
                bar_arrive(5 + st);
            }
        };

        auto zacc = [&]() {
#pragma unroll
            for (int mi = 0; mi < 4; mi++)
#pragma unroll
                for (int ni = 0; ni < 4; ni++)
#pragma unroll
                    for (int r = 0; r < 4; r++) acc[mi][ni][r] = 0.f;
        };

        auto epi = [&](const float* sb, float* cbuf, __nv_bfloat16* hdst,
                       float* hfp) {
            bar9();                               // prior zb readers done
            const int gid = lane >> 2, t4 = lane & 3;
#pragma unroll
            for (int mi = 0; mi < 4; mi++) {
                int r0 = wm + mi * 16 + gid;
#pragma unroll
                for (int ni = 0; ni < 4; ni++) {
                    int c = wn + ni * 8 + t4 * 2;
                    *(float2*)&zb[(size_t)r0 * 132 + c]       = make_float2(acc[mi][ni][0], acc[mi][ni][1]);
                    *(float2*)&zb[(size_t)(r0 + 8) * 132 + c] = make_float2(acc[mi][ni][2], acc[mi][ni][3]);
                }
            }
            bar9();                               // zb visible to consumers
            for (int idx = tid; idx < 4096; idx += 256) {
                const int row = idx >> 5;
                const int j   = idx & 31;
                const int m   = m0 + row;
                const float* zr = zb + (size_t)row * 132;
                float zi = zr[j]      + sb[j];
                float zf = zr[32 + j] + sb[32 + j];
                float zg = zr[64 + j] + sb[64 + j];
                float zo = zr[96 + j] + sb[96 + j];
                float* cp_ = cbuf + (size_t)m * HD + j0 + j;
                float c = sig_a(zf) * (*cp_) + sig_a(zi) * tanh_a(zg);
                *cp_ = c;
                float h = sig_a(zo) * tanh_a(c);
                hdst[(size_t)m * 1024 + j0 + j] = __float2bfloat16(h);
                if (hfp) hfp[(size_t)m * HD + j0 + j] = h;
            }
        };

        if (d0) {
            zacc();
            consume(0, 10);
            epi(sbias, c0buf, h0dst, nullptr);   // producer streams l1 meanwhile
        }
        if (d1) {
            zacc();
            consume(n0, 16);
            epi(sbias + 128, c1buf, h1dst, h1fp);
        }
    }
    // groupbar() at call site provides the full-CTA sync + visibility
}

// ---------------- fc phase: group-local (16 CTAs of one m-group) -------------
__device__ void fc_group(char* smem,
                         const float* __restrict__ fcw,
                         const float* __restrict__ fcb,
                         float* __restrict__ out, int t)
{
    const int gq = blockIdx.x >> 4, jx = blockIdx.x & 15;
    const int r0 = gq * 128 + jx * 8;
    const int tid = threadIdx.x;
    float* hs = (float*)smem;                  // 8 x 512 fp32

    for (int i = tid * 4; i < 8 * HD; i += NTHR * 4) {
        int rr = i >> 9, u = i & 511;
        *(float4*)(hs + rr * HD + u) = ldcg4(g_h1f + (size_t)(r0 + rr) * HD + u);
    }
    __syncthreads();

    if (tid < 256) {
        const int col   = tid & 127;
        const int rbase = tid >> 7;
        float a0 = 0.f, a1 = 0.f, a2 = 0.f, a3 = 0.f;
        const float4* w = (const float4*)(fcw + (size_t)col * HD);
        const float* h0p = hs + (rbase + 0) * HD;
        const float* h1p = hs + (rbase + 2) * HD;
        const float* h2p = hs + (rbase + 4) * HD;
        const float* h3p = hs + (rbase + 6) * HD;
#pragma unroll 4
        for (int k4 = 0; k4 < HD / 4; k4++) {
            float4 wv = __ldg(w + k4);
            float4 x0 = *(const float4*)(h0p + k4 * 4);
            float4 x1 = *(const float4*)(h1p + k4 * 4);
            float4 x2 = *(const float4*)(h2p + k4 * 4);
            float4 x3 = *(const float4*)(h3p + k4 * 4);
            a0 += x0.x * wv.x + x0.y * wv.y + x0.z * wv.z + x0.w * wv.w;
            a1 += x1.x * wv.x + x1.y * wv.y + x1.z * wv.z + x1.w * wv.w;
            a2 += x2.x * wv.x + x2.y * wv.y + x2.z * wv.z + x2.w * wv.w;
            a3 += x3.x * wv.x + x3.y * wv.y + x3.z * wv.z + x3.w * wv.w;
        }
        float b = fcb[col];
        float r[4] = {a0 + b, a1 + b, a2 + b, a3 + b};
#pragma unroll
        for (int i = 0; i < 4; i++) {
            int m = r0 + rbase + 2 * i;
            out[(size_t)m * (TDEC * ID) + (size_t)t * ID + col] = r[i];
            g_din[(size_t)m * ID + col] = __float2bfloat16(r[i]);
        }
    }
    __syncthreads();
}

// ---------------- persistent kernel -----------------------------------------
__global__ void __launch_bounds__(NTHR, 1)
lstm_persistent(const float* __restrict__ x,
                const float* __restrict__ Wih0, const float* __restrict__ Whh0,
                const float* __restrict__ bih0, const float* __restrict__ bhh0,
                const float* __restrict__ Wih1, const float* __restrict__ Whh1,
                const float* __restrict__ bih1, const float* __restrict__ bhh1,
                const float* __restrict__ fcw,  const float* __restrict__ fcb,
                float* __restrict__ out)
{
    extern __shared__ char dyn[];        // NST*STB + ZBF*4 = 215040 B
    __shared__ float s_bias[256];
    float* zb = (float*)(dyn + NST * STB);

    // prime EMPTY barriers (one consumer arrival round per stage)
    if (threadIdx.x < 256) {
        bar_arrive(5); bar_arrive(6); bar_arrive(7); bar_arrive(8);
    }

    // preload per-CTA gate biases once (layer0 -> [0..127], layer1 -> [128..255])
    {
        const int j0 = (blockIdx.x & 15) * 32;
        if (threadIdx.x < 128) {
            int n = (threadIdx.x >> 5) * 512 + j0 + (threadIdx.x & 31);
            s_bias[threadIdx.x]       = bih0[n] + bhh0[n];
            s_bias[128 + threadIdx.x] = bih1[n] + bhh1[n];
        }
    }

    init_phase(x, Wih0, Whh0, Wih1, Whh1);
    gridbar();                           // ONLY global barrier

    // ======== encoder: fused wavefront {layer0[p], layer1[p-1]}, 1 pipe ======
    for (int p = 0; p <= TENC; p++) {
        int d0 = (p < TENC), d1 = (p >= 1);
        __nv_bfloat16* b_p  = (p & 1) ? g_hB : g_hA;   // parity of t = p
        __nv_bfloat16* b_pm = (p & 1) ? g_hA : g_hB;   // parity of t = p-1
        int tx = d0 ? p : (TENC - 1);                  // safe index
        phase_fused(dyn, zb, s_bias, d0, d1,
                    g_xb + (size_t)tx * ID, (size_t)TENC * ID,
                    b_pm, g_c0, b_p,                   // layer0: prev h0, write h0[p]
                    b_pm, b_p + 512,                   // layer1: h0[p-1], h1[p-2]
                    g_c1, b_pm + 512, nullptr);        //          write h1[p-1]
        groupbar();
    }

    // ======== decoder: serial per step ========
    for (int t = 0; t < TDEC; t++) {
        __nv_bfloat16* b_t  = (t & 1) ? g_hB : g_hA;   // parity continues
        __nv_bfloat16* b_tm = (t & 1) ? g_hA : g_hB;
        phase_fused(dyn, zb, s_bias, 1, 0,
                    g_din, ID,
                    b_tm, g_c0, b_t,
                    nullptr, nullptr, nullptr, nullptr, nullptr);
        groupbar();
        phase_fused(dyn, zb, s_bias, 0, 1,
                    nullptr, 0,
                    nullptr, nullptr, nullptr,
                    b_t, b_tm + 512,
                    g_c1, b_t + 512, g_h1f);
        groupbar();
        fc_group(dyn, fcw, fcb, out, t);
        groupbar();
    }
}

// ---------------- entry ------------------------------------------------------
extern "C" void kernel_launch(void* const* d_in, const int* in_sizes, int n_in,
                              void* d_out, int out_size)
{
    const int smem = NST * STB + ZBF * 4;    // 147456 + 67584 = 215040
    cudaFuncSetAttribute(lstm_persistent,
                         cudaFuncAttributeMaxDynamicSharedMemorySize, smem);
    lstm_persistent<<<NBLK, NTHR, smem>>>(
        (const float*)d_in[0],
        (const float*)d_in[1], (const float*)d_in[2],
        (const float*)d_in[3], (const float*)d_in[4],
        (const float*)d_in[5], (const float*)d_in[6],
        (const float*)d_in[7], (const float*)d_in[8],
        (const float*)d_in[9], (const float*)d_in[10],
        (float*)d_out);
}

// round 17
// speedup vs baseline: 1.0729x; 1.0729x over previous
#include <cuda_runtime.h>
#include <cuda_bf16.h>
#include <math.h>
#include <cstdint>

#define BD   1024
#define HD   512
#define TENC 384
#define TDEC 128
#define ID   128
#define NBLK 128
#define NTHR 640           // 16 consumer warps + 4 producer warps

#define ROWB 144           // smem row stride bytes (64 bf16 = 128B + 16B pad)
#define TILEB (128 * ROWB) // 18432 per operand tile
#define STB  (2 * TILEB)   // 36864 per stage (A + B)
#define NST  4             // ring depth (power of two)

#define BAR_CNT 640        // named barriers: FULL[st]=1+st, EMPTY[st]=5+st
#define NGRP   8           // m-groups of 16 CTAs each

// ---------------- static device scratch ------------------------------------
__device__ __align__(16) __nv_bfloat16 g_hA[BD * 1024];   // ping-pong [h0|h1]
__device__ __align__(16) __nv_bfloat16 g_hB[BD * 1024];
__device__ __align__(16) float         g_h1f[BD * HD];    // fp32 h1 for fc
__device__ __align__(16) float g_c0 [BD * HD];
__device__ __align__(16) float g_c1 [BD * HD];
__device__ __align__(16) __nv_bfloat16 g_din[BD * ID];
__device__ __align__(16) __nv_bfloat16 g_xb [BD * TENC * ID];   // bf16 x copy
__device__ __align__(16) __nv_bfloat16 g_rWih0[2048 * 128];
__device__ __align__(16) __nv_bfloat16 g_rWhh0[2048 * 512];
__device__ __align__(16) __nv_bfloat16 g_rWih1[2048 * 512];
__device__ __align__(16) __nv_bfloat16 g_rWhh1[2048 * 512];
__device__ unsigned          g_bar_cnt;
__device__ volatile unsigned g_bar_gen;
__device__ unsigned          g_gcnt[NGRP * 64];
__device__ volatile unsigned g_ggen[NGRP * 64];

// ---------------- helpers --------------------------------------------------
__device__ __forceinline__ uint32_t smem_u32(const void* p) {
    uint32_t a;
    asm("{ .reg .u64 t; cvta.to.shared.u64 t, %1; cvt.u32.u64 %0, t; }"
        : "=r"(a) : "l"(p));
    return a;
}
__device__ __forceinline__ float tanh_a(float x) {
    float r;
    asm("tanh.approx.f32 %0, %1;" : "=f"(r) : "f"(x));
    return r;
}
__device__ __forceinline__ float sig_a(float x) {
    return fmaf(0.5f, tanh_a(0.5f * x), 0.5f);
}
__device__ __forceinline__ void cp16(uint32_t dst, const void* src) {
    asm volatile("cp.async.cg.shared.global [%0], [%1], 16;"
                 :: "r"(dst), "l"(src) : "memory");
}
__device__ __forceinline__ void mma16(float* c, uint32_t a0, uint32_t a1,
                                      uint32_t a2, uint32_t a3,
                                      uint32_t b0, uint32_t b1) {
    asm volatile("mma.sync.aligned.m16n8k16.row.col.f32.bf16.bf16.f32 "
                 "{%0,%1,%2,%3}, {%4,%5,%6,%7}, {%8,%9}, {%0,%1,%2,%3};"
                 : "+f"(c[0]), "+f"(c[1]), "+f"(c[2]), "+f"(c[3])
                 : "r"(a0), "r"(a1), "r"(a2), "r"(a3), "r"(b0), "r"(b1));
}
#define LDSM4(r, a)                                                          \
    asm volatile("ldmatrix.sync.aligned.m8n8.x4.shared.b16 {%0,%1,%2,%3}, [%4];" \
        : "=r"((r)[0]), "=r"((r)[1]), "=r"((r)[2]), "=r"((r)[3]) : "r"(a))

__device__ __forceinline__ float4 ldcg4(const float* p) {
    float4 v;
    asm volatile("ld.global.cg.v4.f32 {%0,%1,%2,%3}, [%4];"
                 : "=f"(v.x), "=f"(v.y), "=f"(v.z), "=f"(v.w) : "l"(p));
    return v;
}
__device__ __forceinline__ void bar_sync(int id) {
    asm volatile("bar.sync %0, %1;" :: "r"(id), "n"(BAR_CNT) : "memory");
}
__device__ __forceinline__ void bar_arrive(int id) {
    asm volatile("bar.arrive %0, %1;" :: "r"(id), "n"(BAR_CNT) : "memory");
}

// ---------------- barriers ---------------------------------------------------
__device__ __forceinline__ void gridbar() {
    __syncthreads();
    if (threadIdx.x == 0) {
        unsigned gen = g_bar_gen;
        __threadfence();
        if (atomicAdd(&g_bar_cnt, 1u) == NBLK - 1u) {
            g_bar_cnt = 0u;
            __threadfence();
            g_bar_gen = gen + 1u;
        } else {
            while (g_bar_gen == gen) { __nanosleep(32); }
        }
        __threadfence();
    }
    __syncthreads();
}
__device__ __forceinline__ void groupbar() {
    const int gq = (blockIdx.x >> 4) * 64;
    __syncthreads();
    if (threadIdx.x == 0) {
        unsigned gen = g_ggen[gq];
        __threadfence();
        if (atomicAdd(&g_gcnt[gq], 1u) == 15u) {
            g_gcnt[gq] = 0u;
            __threadfence();
            g_ggen[gq] = gen + 1u;
        } else {
            while (g_ggen[gq] == gen) { __nanosleep(32); }
        }
        __threadfence();
    }
    __syncthreads();
}

// ---------------- init ------------------------------------------------------
__device__ __forceinline__ uint32_t packbf(float a, float b) {
    __nv_bfloat162 v = __floats2bfloat162_rn(a, b);
    return *(uint32_t*)&v;
}
__device__ void cvt_arr(const float* __restrict__ src, __nv_bfloat16* dst,
                        int n, int g, int GT)
{
    const float4* s4 = (const float4*)src;
    uint2* d4 = (uint2*)dst;
    for (int i = g; i < n / 4; i += GT) {
        float4 v = s4[i];
        d4[i] = make_uint2(packbf(v.x, v.y), packbf(v.z, v.w));
    }
}
__device__ void init_phase(const float* __restrict__ x,
                           const float* __restrict__ Wih0,
                           const float* __restrict__ Whh0,
                           const float* __restrict__ Wih1,
                           const float* __restrict__ Whh1)
{
    const int g = blockIdx.x * NTHR + threadIdx.x;
    const int GT = NBLK * NTHR;
    uint32_t* hA = (uint32_t*)g_hA;
    uint32_t* hB = (uint32_t*)g_hB;
    for (int i = g; i < BD * 1024 / 2; i += GT) { hA[i] = 0u; hB[i] = 0u; }
    for (int i = g; i < BD * HD; i += GT) { g_c0[i] = 0.f; g_c1[i] = 0.f; }
    for (int i = g; i < BD * ID; i += GT) {
        int b = i >> 7, col = i & 127;
        g_din[i] = __float2bfloat16(
            x[(size_t)b * (TENC * ID) + (size_t)(TENC - 1) * ID + col]);
    }
    cvt_arr(x,    g_xb,    BD * TENC * ID, g, GT);
    cvt_arr(Wih0, g_rWih0, 2048 * 128, g, GT);
    cvt_arr(Whh0, g_rWhh0, 2048 * 512, g, GT);
    cvt_arr(Wih1, g_rWih1, 2048 * 512, g, GT);
    cvt_arr(Whh1, g_rWhh1, 2048 * 512, g, GT);
}

// ---------------- fused GEMM + gates phase (warp-specialized, bf16) ---------
// CTA tile: 128 batch rows x 128 gate cols ({i,f,g,o} x 32 j at j0).
// Warps 0-15: consumers (4x4 grid, 32m x 32n). Warps 16-19: producers.
__device__ void phase_layer(char* smem, float* sbias,
                            const __nv_bfloat16* A1, size_t lda1, int KA1,
                            const __nv_bfloat16* A2, int lda2,
                            const __nv_bfloat16* W1, int ldw1, int KW1,
                            const __nv_bfloat16* W2, int ldw2,
                            const float* bih, const float* bhh,
                            float* cbuf, __nv_bfloat16* hdst, float* hfp,
                            int KT)
{
    const int tid  = threadIdx.x;
    const int warp = tid >> 5, lane = tid & 31;
    const int m0 = (blockIdx.x >> 4) * 128;
    const int j0 = (blockIdx.x & 15) * 32;
    const int nch = KT >> 6;             // #k64 chunks (10 or 16)

    if (tid < 128) {
        int n = (tid >> 5) * 512 + j0 + (tid & 31);
        sbias[tid] = bih[n] + bhh[n];
    }

    const uint32_t sA = smem_u32(smem);
    const uint32_t sB = sA + (uint32_t)TILEB;

    if (warp >= 16) {
        // ================= producer path =================
        const int p = tid - 512;                   // 0..127
        const uint32_t dA = sA + (uint32_t)p * ROWB;
        const uint32_t dB = sB + (uint32_t)p * ROWB;
        const int nrow = (p >> 5) * 512 + j0 + (p & 31);
        const __nv_bfloat16* a1r = A1 + (size_t)(m0 + p) * lda1;
        const __nv_bfloat16* a2r = A2 + (size_t)(m0 + p) * lda2 - KA1;
        const __nv_bfloat16* w1r = W1 + (size_t)nrow * ldw1;
        const __nv_bfloat16* w2r = W2 + (size_t)nrow * ldw2 - KW1;

        for (int ch = 0; ch < nch; ch++) {
            int st = ch & (NST - 1);
            int k0 = ch * 64;
            bar_sync(5 + st);                      // stage free?
            const __nv_bfloat16* srcA = (k0 < KA1) ? a1r + k0 : a2r + k0;
            const __nv_bfloat16* srcB = (k0 < KW1) ? w1r + k0 : w2r + k0;
            uint32_t da = dA + (uint32_t)st * STB;
            uint32_t db = dB + (uint32_t)st * STB;
#pragma unroll
            for (int q = 0; q < 8; q++) {          // 8 x 16B = 128B per row
                cp16(da + q * 16u, srcA + q * 8);
                cp16(db + q * 16u, srcB + q * 8);
            }
            asm volatile("cp.async.commit_group;" ::: "memory");
            if (ch > 0) {
                asm volatile("cp.async.wait_group 1;" ::: "memory");
                bar_arrive(1 + ((ch - 1) & (NST - 1)));
            }
        }
        asm volatile("cp.async.wait_group 0;" ::: "memory");
        bar_arrive(1 + ((nch - 1) & (NST - 1)));
    } else {
        // ================= consumer path (32m x 32n warp tile) =================
        const int wm = (warp >> 2) * 32;
        const int wn = (warp & 3) * 32;
        const uint32_t offA = sA + (uint32_t)((lane & 15) * ROWB)
                                 + (uint32_t)((lane >> 4) * 16)
                                 + (uint32_t)wm * ROWB;
        const uint32_t offB = sB + (uint32_t)((lane & 15) * ROWB)
                                 + (uint32_t)((lane >> 4) * 16)
                                 + (uint32_t)wn * ROWB;

        float acc[2][4][4];
#pragma unroll
        for (int mi = 0; mi < 2; mi++)
#pragma unroll
            for (int ni = 0; ni < 4; ni++)
#pragma unroll
                for (int r = 0; r < 4; r++) acc[mi][ni][r] = 0.f;

        for (int ch = 0; ch < nch; ch++) {
            int st = ch & (NST - 1);
            bar_sync(1 + st);                      // wait stage full
            const uint32_t so = (uint32_t)st * STB;
#pragma unroll
            for (int ks = 0; ks < 4; ks++) {       // four k16 steps of k64
                const uint32_t ko = (uint32_t)(ks * 32);
                uint32_t fb0[4], fb1[4], fa0[4], fa1[4];
                LDSM4(fb0, offB + so + ko);                      // n 0-15
                LDSM4(fb1, offB + so + 16u * ROWB + ko);         // n 16-31
                LDSM4(fa0, offA + so + ko);                      // m +0
                LDSM4(fa1, offA + so + 16u * ROWB + ko);         // m +16
                mma16(acc[0][0], fa0[0], fa0[1], fa0[2], fa0[3], fb0[0], fb0[2]);
                mma16(acc[0][1], fa0[0], fa0[1], fa0[2], fa0[3], fb0[1], fb0[3]);
                mma16(acc[0][2], fa0[0], fa0[1], fa0[2], fa0[3], fb1[0], fb1[2]);
                mma16(acc[0][3], fa0[0], fa0[1], fa0[2], fa0[3], fb1[1], fb1[3]);
                mma16(acc[1][0], fa1[0], fa1[1], fa1[2], fa1[3], fb0[0], fb0[2]);
                mma16(acc[1][1], fa1[0], fa1[1], fa1[2], fa1[3], fb0[1], fb0[3]);
                mma16(acc[1][2], fa1[0], fa1[1], fa1[2], fa1[3], fb1[0], fb1[2]);
                mma16(acc[1][3], fa1[0], fa1[1], fa1[2], fa1[3], fb1[1], fb1[3]);
            }
            bar_arrive(5 + st);                    // stage consumed
        }

        __syncthreads();                           // pair with producers below
        {
            const int gid = lane >> 2, t4 = lane & 3;
            float* zb = (float*)smem;
#pragma unroll
            for (int mi = 0; mi < 2; mi++) {
                int r0 = wm + mi * 16 + gid;
#pragma unroll
                for (int ni = 0; ni < 4; ni++) {
                    int c = wn + ni * 8 + t4 * 2;
                    *(float2*)&zb[(size_t)r0 * 132 + c]       = make_float2(acc[mi][ni][0], acc[mi][ni][1]);
                    *(float2*)&zb[(size_t)(r0 + 8) * 132 + c] = make_float2(acc[mi][ni][2], acc[mi][ni][3]);
                }
            }
        }
    }

    if (warp >= 16) __syncthreads();               // producers' pairing sync
    __syncthreads();                               // zb visible to all

    // ---- gate epilogue over ALL 640 threads ----
    {
        float* zb = (float*)smem;
        for (int idx = tid; idx < 4096; idx += NTHR) {
            const int row = idx >> 5;              // 0..127
            const int j   = idx & 31;
            const int m   = m0 + row;
            const float* zr = zb + (size_t)row * 132;
            float zi = zr[j]      + sbias[j];
            float zf = zr[32 + j] + sbias[32 + j];
            float zg = zr[64 + j] + sbias[64 + j];
            float zo = zr[96 + j] + sbias[96 + j];
            float* cp_ = cbuf + (size_t)m * HD + j0 + j;
            float c = sig_a(zf) * (*cp_) + sig_a(zi) * tanh_a(zg);
            *cp_ = c;
            float h = sig_a(zo) * tanh_a(c);
            hdst[(size_t)m * 1024 + j0 + j] = __float2bfloat16(h);
            if (hfp) hfp[(size_t)m * HD + j0 + j] = h;
        }
    }
    __syncthreads();
}

// ---------------- fc phase: group-local (16 CTAs of one m-group) -------------
__device__ void fc_group(char* smem,
                         const float* __restrict__ fcw,
                         const float* __restrict__ fcb,
                         float* __restrict__ out, int t)
{
    const int gq = blockIdx.x >> 4, jx = blockIdx.x & 15;
    const int r0 = gq * 128 + jx * 8;          // this CTA's 8 batch rows
    const int tid = threadIdx.x;
    float* hs = (float*)smem;                  // 8 x 512 fp32

    for (int i = tid * 4; i < 8 * HD; i += NTHR * 4) {
        int rr = i >> 9, u = i & 511;
        *(float4*)(hs + rr * HD + u) = ldcg4(g_h1f + (size_t)(r0 + rr) * HD + u);
    }
    __syncthreads();

    if (tid < 256) {
        const int col   = tid & 127;
        const int rbase = tid >> 7;            // 0 or 1; rows rbase+2i
        float a0 = 0.f, a1 = 0.f, a2 = 0.f, a3 = 0.f;
        const float4* w = (const float4*)(fcw + (size_t)col * HD);
        const float* h0p = hs + (rbase + 0) * HD;
        const float* h1p = hs + (rbase + 2) * HD;
        const float* h2p = hs + (rbase + 4) * HD;
        const float* h3p = hs + (rbase + 6) * HD;
#pragma unroll 4
        for (int k4 = 0; k4 < HD / 4; k4++) {
            float4 wv = __ldg(w + k4);
            float4 x0 = *(const float4*)(h0p + k4 * 4);
            float4 x1 = *(const float4*)(h1p + k4 * 4);
            float4 x2 = *(const float4*)(h2p + k4 * 4);
            float4 x3 = *(const float4*)(h3p + k4 * 4);
            a0 += x0.x * wv.x + x0.y * wv.y + x0.z * wv.z + x0.w * wv.w;
            a1 += x1.x * wv.x + x1.y * wv.y + x1.z * wv.z + x1.w * wv.w;
            a2 += x2.x * wv.x + x2.y * wv.y + x2.z * wv.z + x2.w * wv.w;
            a3 += x3.x * wv.x + x3.y * wv.y + x3.z * wv.z + x3.w * wv.w;
        }
        float b = fcb[col];
        float r[4] = {a0 + b, a1 + b, a2 + b, a3 + b};
#pragma unroll
        for (int i = 0; i < 4; i++) {
            int m = r0 + rbase + 2 * i;
            out[(size_t)m * (TDEC * ID) + (size_t)t * ID + col] = r[i];
            g_din[(size_t)m * ID + col] = __float2bfloat16(r[i]);
        }
    }
    __syncthreads();
}

// ---------------- persistent kernel -----------------------------------------
__global__ void __launch_bounds__(NTHR, 1)
lstm_persistent(const float* __restrict__ x,
                const float* __restrict__ Wih0, const float* __restrict__ Whh0,
                const float* __restrict__ bih0, const float* __restrict__ bhh0,
                const float* __restrict__ Wih1, const float* __restrict__ Whh1,
                const float* __restrict__ bih1, const float* __restrict__ bhh1,
                const float* __restrict__ fcw,  const float* __restrict__ fcb,
                float* __restrict__ out)
{
    extern __shared__ char dyn[];        // NST * STB = 147456 B
    __shared__ float s_bias[128];

    // prime EMPTY barriers: one consumer-side arrival round per stage
    if (threadIdx.x < 512) {
        bar_arrive(5); bar_arrive(6); bar_arrive(7); bar_arrive(8);
    }

    init_phase(x, Wih0, Whh0, Wih1, Whh1);
    gridbar();                           // ONLY global barrier

    // ======== encoder: wavefront {layer0[p], layer1[p-1]} per phase ========
    for (int p = 0; p <= TENC; p++) {
        if (p < TENC) {
            int t = p;
            __nv_bfloat16* cur  = (t & 1) ? g_hB : g_hA;
            __nv_bfloat16* prev = (t & 1) ? g_hA : g_hB;
            phase_layer(dyn, s_bias,
                        g_xb + (size_t)t * ID, (size_t)TENC * ID, 128, prev, 1024,
                        g_rWih0, 128, 128, g_rWhh0, 512,
                        bih0, bhh0, g_c0, cur, nullptr, 640);
        }
        if (p >= 1) {
            int t1 = p - 1;
            __nv_bfloat16* cur  = (t1 & 1) ? g_hB : g_hA;
            __nv_bfloat16* prev = (t1 & 1) ? g_hA : g_hB;
            phase_layer(dyn, s_bias,
                        cur, 1024, 512, prev + 512, 1024,
                        g_rWih1, 512, 512, g_rWhh1, 512,
                        bih1, bhh1, g_c1, cur + 512, nullptr, 1024);
        }
        groupbar();
    }

    // ======== decoder: serial per step, group-local barriers ========
    for (int t = 0; t < TDEC; t++) {
        __nv_bfloat16* cur  = (t & 1) ? g_hB : g_hA;   // TENC even: parity ok
        __nv_bfloat16* prev = (t & 1) ? g_hA : g_hB;
        phase_layer(dyn, s_bias,
                    g_din, ID, 128, prev, 1024,
                    g_rWih0, 128, 128, g_rWhh0, 512,
                    bih0, bhh0, g_c0, cur, nullptr, 640);
        groupbar();
        phase_layer(dyn, s_bias,
                    cur, 1024, 512, prev + 512, 1024,
                    g_rWih1, 512, 512, g_rWhh1, 512,
                    bih1, bhh1, g_c1, cur + 512, g_h1f, 1024);
        groupbar();
        fc_group(dyn, fcw, fcb, out, t);
        groupbar();
    }
}

// ---------------- entry ------------------------------------------------------
extern "C" void kernel_launch(void* const* d_in, const int* in_sizes, int n_in,
                              void* d_out, int out_size)
{
    const int smem = NST * STB;          // 147456
    cudaFuncSetAttribute(lstm_persistent,
                         cudaFuncAttributeMaxDynamicSharedMemorySize, smem);
    lstm_persistent<<<NBLK, NTHR, smem>>>(
        (const float*)d_in[0],
        (const float*)d_in[1], (const float*)d_in[2],
        (const float*)d_in[3], (const float*)d_in[4],
        (const float*)d_in[5], (const float*)d_in[6],
        (const float*)d_in[7], (const float*)d_in[8],
        (const float*)d_in[9], (const float*)d_in[10],
        (float*)d_out);
}